// round 11
// baseline (speedup 1.0000x reference)
#include <cuda_runtime.h>
#include <cstdint>

// FeatureEmbeddingBank: 24 single-token lookups + 8 multi-token (len 20)
// mean-pooled lookups. B=4096, EMB=64, VOCAB=100000 (+1 pad row 0).
//
// d_in[0] = int_feats  int32  [4096, 184]
// d_in[1] = W          fp32   [32, 100001, 64]
// d_out   =            fp32   [4096, 32, 64]
//
// Fused single-kernel design (one launch):
//   blocks [0, NB_MULTI):   multi features, 1 warp per (b, m) pair,
//     m-major warp ordering (<=2 feature slices live in L2 at once).
//     Per warp: lane < 20 loads one token index (coalesced, evict-first),
//     shfl-broadcast; nonzero count via one ballot. Lanes 0-15 gather
//     tokens 0-9, lanes 16-31 tokens 10-19; each lane owns one float4 of
//     the 256 B row; gathers in 2 chunks of 5 in-flight LDG.128 with
//     DEFAULT caching (only stream with reuse -> keep it in L2).
//   blocks [NB_MULTI, ..):  single features, 2 independent (b,f) pairs per
//     thread, loaded with __ldcs (unique rows, evict-first -> no pollution).
//   ALL output stores use __stcs (streaming) so 32 MB of writes do not
//   evict reusable multi-feature rows from L2.

namespace {
constexpr int N_SINGLE  = 24;
constexpr int N_MULTI   = 8;
constexpr int MULTI_LEN = 20;
constexpr int HALF_LEN  = MULTI_LEN / 2;           // 10
constexpr int CHUNK     = 5;                       // gathers in flight per chunk
constexpr int N_FEAT    = N_SINGLE + N_MULTI;      // 32
constexpr int VOCAB     = 100000;
constexpr int EMB       = 64;
constexpr int TOTAL_W   = N_SINGLE + N_MULTI * MULTI_LEN;  // 184
constexpr int ROW_F4    = EMB / 4;                 // 16 float4 per row
constexpr int BATCH     = 4096;                    // power of two

constexpr int THREADS   = 256;                     // 8 warps

// multi: 1 warp per (b,m) pair -> 4096*8 / 8 warps = 4096 blocks
constexpr int NB_MULTI  = BATCH * N_MULTI / (THREADS / 32);     // 4096
// single: 32 pairs per block (16 groups x 2 pairs per thread)
constexpr int PAIRS_PER_BLOCK = 2 * (THREADS / 16);             // 32
constexpr int NB_SINGLE = BATCH * N_SINGLE / PAIRS_PER_BLOCK;   // 3072
constexpr int NB_TOTAL  = NB_MULTI + NB_SINGLE;                 // 7168
}

__global__ __launch_bounds__(THREADS, 6)
void feb_fused(const int* __restrict__ idx,
               const float4* __restrict__ W,
               float4* __restrict__ out)
{
    const int bid = blockIdx.x;

    if (bid < NB_MULTI) {
        // ---------------- multi-token path: one warp per (b, m) ----------------
        const int wid  = bid * (THREADS / 32) + (threadIdx.x >> 5);
        const int lane = threadIdx.x & 31;

        // m-major ordering: feature index is the SLOW coordinate so that
        // concurrent blocks share (at most ~2) feature slices in L2.
        const int m = wid >> 12;                 // wid / BATCH
        const int b = wid & (BATCH - 1);         // wid % BATCH
        const int f = N_SINGLE + m;

        const int half = lane >> 4;              // 0: tokens 0-9, 1: tokens 10-19
        const int sub  = lane & 15;              // float4 slot within the row

        // One coalesced index load per warp (lanes 0-19), shfl-broadcast.
        // Indices are read exactly once -> evict-first.
        const int* __restrict__ p =
            idx + (size_t)b * TOTAL_W + N_SINGLE + m * MULTI_LEN;
        int myv = 0;
        if (lane < MULTI_LEN) {
            myv = __ldcs(p + lane);
            myv = min(max(myv, 0), VOCAB);       // clip once, pre-broadcast
        }

        // Nonzero-token count: one ballot over the 20 index lanes.
        const unsigned nz = __ballot_sync(0xffffffffu, myv != 0 && lane < MULTI_LEN);
        const int cnt = __popc(nz);

        const float4* __restrict__ Wf =
            W + (size_t)f * (VOCAB + 1) * ROW_F4 + sub;

        float ax = 0.f, ay = 0.f, az = 0.f, aw = 0.f;

        // Two chunks of CHUNK gathers; within a chunk all loads are
        // independent and simultaneously in flight (20 data regs).
        // Default caching: this is the only stream with L2 reuse.
#pragma unroll
        for (int c = 0; c < HALF_LEN / CHUNK; ++c) {
            float4 e[CHUNK];
#pragma unroll
            for (int t = 0; t < CHUNK; ++t) {
                const int v = __shfl_sync(0xffffffffu, myv,
                                          half * HALF_LEN + c * CHUNK + t);
                e[t] = __ldg(Wf + (size_t)v * ROW_F4);
            }
#pragma unroll
            for (int t = 0; t < CHUNK; ++t) {
                ax += e[t].x; ay += e[t].y; az += e[t].z; aw += e[t].w;
            }
        }

        // combine the two token-halves across the warp
        ax += __shfl_xor_sync(0xffffffffu, ax, 16);
        ay += __shfl_xor_sync(0xffffffffu, ay, 16);
        az += __shfl_xor_sync(0xffffffffu, az, 16);
        aw += __shfl_xor_sync(0xffffffffu, aw, 16);

        if (half == 0) {
            const float inv = 1.0f / (float)max(cnt, 1);
            __stcs(&out[((size_t)b * N_FEAT + f) * ROW_F4 + sub],
                   make_float4(ax * inv, ay * inv, az * inv, aw * inv));
        }
    } else {
        // -------- single-token path: 2 independent (b, f) pairs per thread -----
        const int group = threadIdx.x >> 4;      // 0..15
        const int lane  = threadIdx.x & 15;      // float4 slot

        const int pair0 = (bid - NB_MULTI) * PAIRS_PER_BLOCK + group;
        const int pair1 = pair0 + (THREADS / 16);    // +16

        const int b0 = pair0 / N_SINGLE, f0 = pair0 - b0 * N_SINGLE;
        const int b1 = pair1 / N_SINGLE, f1 = pair1 - b1 * N_SINGLE;

        int v0 = __ldcs(idx + (size_t)b0 * TOTAL_W + f0);
        int v1 = __ldcs(idx + (size_t)b1 * TOTAL_W + f1);
        v0 = min(max(v0, 0), VOCAB);
        v1 = min(max(v1, 0), VOCAB);

        // ~98% unique rows -> stream through L2 evict-first, don't pollute.
        const float4 e0 =
            __ldcs(W + ((size_t)f0 * (VOCAB + 1) + (size_t)v0) * ROW_F4 + lane);
        const float4 e1 =
            __ldcs(W + ((size_t)f1 * (VOCAB + 1) + (size_t)v1) * ROW_F4 + lane);

        __stcs(&out[((size_t)b0 * N_FEAT + f0) * ROW_F4 + lane], e0);
        __stcs(&out[((size_t)b1 * N_FEAT + f1) * ROW_F4 + lane], e1);
    }
}

// ---------------------------------------------------------------------------
extern "C" void kernel_launch(void* const* d_in, const int* in_sizes, int n_in,
                              void* d_out, int out_size)
{
    const int*    idx = (const int*)d_in[0];
    const float4* W   = (const float4*)d_in[1];
    float4*       out = (float4*)d_out;

    (void)in_sizes; (void)n_in; (void)out_size;

    feb_fused<<<NB_TOTAL, THREADS>>>(idx, W, out);
}

// round 12
// speedup vs baseline: 1.1232x; 1.1232x over previous
#include <cuda_runtime.h>
#include <cstdint>

// FeatureEmbeddingBank: 24 single-token lookups + 8 multi-token (len 20)
// mean-pooled lookups. B=4096, EMB=64, VOCAB=100000 (+1 pad row 0).
//
// d_in[0] = int_feats  int32  [4096, 184]
// d_in[1] = W          fp32   [32, 100001, 64]
// d_out   =            fp32   [4096, 32, 64]
//
// Converged configuration (best measured across 6 variants):
//   - Fused single kernel, multi blocks first (tail backfilled by singles).
//   - Multi path: 1 warp per (b, m); lanes 0-15 own tokens 0-9, lanes 16-31
//     tokens 10-19; each lane owns one float4 of the 256 B row. Indices are
//     loaded once coalesced (lanes 0-19) and shfl-broadcast; nonzero count
//     via one ballot. Plain loop, default caching, NO launch_bounds cap:
//     ptxas lands ~32 regs -> ~85% occupancy, which measured fastest.
//   - Single path: 2 independent (b, f) pairs per thread (MLP 2).
//   - No cache-policy hints (measured regression), b-major order.

namespace {
constexpr int N_SINGLE  = 24;
constexpr int N_MULTI   = 8;
constexpr int MULTI_LEN = 20;
constexpr int HALF_LEN  = MULTI_LEN / 2;           // 10
constexpr int N_FEAT    = N_SINGLE + N_MULTI;      // 32
constexpr int VOCAB     = 100000;
constexpr int EMB       = 64;
constexpr int TOTAL_W   = N_SINGLE + N_MULTI * MULTI_LEN;  // 184
constexpr int ROW_F4    = EMB / 4;                 // 16 float4 per row
constexpr int BATCH     = 4096;

constexpr int THREADS   = 256;                     // 8 warps

// multi: 1 warp per (b,m) pair -> 4096*8 / 8 warps = 4096 blocks
constexpr int NB_MULTI  = BATCH * N_MULTI / (THREADS / 32);     // 4096
// single: 32 pairs per block (16 groups x 2 pairs per thread)
constexpr int PAIRS_PER_BLOCK = 2 * (THREADS / 16);             // 32
constexpr int NB_SINGLE = BATCH * N_SINGLE / PAIRS_PER_BLOCK;   // 3072
constexpr int NB_TOTAL  = NB_MULTI + NB_SINGLE;                 // 7168
}

__global__ __launch_bounds__(THREADS)
void feb_fused(const int* __restrict__ idx,
               const float4* __restrict__ W,
               float4* __restrict__ out)
{
    const int bid = blockIdx.x;

    if (bid < NB_MULTI) {
        // ---------------- multi-token path: one warp per (b, m) ----------------
        const int wid  = bid * (THREADS / 32) + (threadIdx.x >> 5);
        const int lane = threadIdx.x & 31;

        const int b = wid >> 3;                  // N_MULTI = 8 (b-major)
        const int m = wid & 7;
        const int f = N_SINGLE + m;

        const int half = lane >> 4;              // 0: tokens 0-9, 1: tokens 10-19
        const int sub  = lane & 15;              // float4 slot within the row

        // One coalesced index load per warp (lanes 0-19), shfl-broadcast.
        const int* __restrict__ p =
            idx + (size_t)b * TOTAL_W + N_SINGLE + m * MULTI_LEN;
        int myv = 0;
        if (lane < MULTI_LEN) {
            myv = __ldg(p + lane);
            myv = min(max(myv, 0), VOCAB);       // clip once, pre-broadcast
        }

        // Nonzero-token count: one ballot over the 20 index lanes.
        const unsigned nz = __ballot_sync(0xffffffffu, myv != 0 && lane < MULTI_LEN);
        const int cnt = __popc(nz);

        const float4* __restrict__ Wf =
            W + (size_t)f * (VOCAB + 1) * ROW_F4 + sub;

        float ax = 0.f, ay = 0.f, az = 0.f, aw = 0.f;

#pragma unroll
        for (int t = 0; t < HALF_LEN; ++t) {
            const int v = __shfl_sync(0xffffffffu, myv, half * HALF_LEN + t);
            const float4 e = __ldg(Wf + (size_t)v * ROW_F4);
            ax += e.x; ay += e.y; az += e.z; aw += e.w;
        }

        // combine the two token-halves across the warp
        ax += __shfl_xor_sync(0xffffffffu, ax, 16);
        ay += __shfl_xor_sync(0xffffffffu, ay, 16);
        az += __shfl_xor_sync(0xffffffffu, az, 16);
        aw += __shfl_xor_sync(0xffffffffu, aw, 16);

        if (half == 0) {
            const float inv = 1.0f / (float)max(cnt, 1);
            out[((size_t)b * N_FEAT + f) * ROW_F4 + sub] =
                make_float4(ax * inv, ay * inv, az * inv, aw * inv);
        }
    } else {
        // -------- single-token path: 2 independent (b, f) pairs per thread -----
        const int group = threadIdx.x >> 4;      // 0..15
        const int lane  = threadIdx.x & 15;      // float4 slot

        const int pair0 = (bid - NB_MULTI) * PAIRS_PER_BLOCK + group;
        const int pair1 = pair0 + (THREADS / 16);    // +16

        const int b0 = pair0 / N_SINGLE, f0 = pair0 - b0 * N_SINGLE;
        const int b1 = pair1 / N_SINGLE, f1 = pair1 - b1 * N_SINGLE;

        int v0 = __ldg(idx + (size_t)b0 * TOTAL_W + f0);
        int v1 = __ldg(idx + (size_t)b1 * TOTAL_W + f1);
        v0 = min(max(v0, 0), VOCAB);
        v1 = min(max(v1, 0), VOCAB);

        const float4 e0 =
            __ldg(W + ((size_t)f0 * (VOCAB + 1) + (size_t)v0) * ROW_F4 + lane);
        const float4 e1 =
            __ldg(W + ((size_t)f1 * (VOCAB + 1) + (size_t)v1) * ROW_F4 + lane);

        out[((size_t)b0 * N_FEAT + f0) * ROW_F4 + lane] = e0;
        out[((size_t)b1 * N_FEAT + f1) * ROW_F4 + lane] = e1;
    }
}

// ---------------------------------------------------------------------------
extern "C" void kernel_launch(void* const* d_in, const int* in_sizes, int n_in,
                              void* d_out, int out_size)
{
    const int*    idx = (const int*)d_in[0];
    const float4* W   = (const float4*)d_in[1];
    float4*       out = (float4*)d_out;

    (void)in_sizes; (void)n_in; (void)out_size;

    feb_fused<<<NB_TOTAL, THREADS>>>(idx, W, out);
}